// round 7
// baseline (speedup 1.0000x reference)
#include <cuda_runtime.h>
#include <cuda_fp16.h>
#include <cstdint>

#define NN   100000
#define EE   1600000
#define CIN  256
#define COUT 128

#define SCAN_B 1024
#define SCAN_NB ((NN + SCAN_B - 1) / SCAN_B)   // 98

// ---------------- scratch (static device globals; no allocation) ----------------
__device__ __half g_feat[(size_t)NN * COUT];  // 25.6 MB -> L2-resident
__device__ int   g_count[NN];
__device__ int   g_off[NN + 1];
__device__ int   g_cur[NN];
__device__ int   g_bsum[SCAN_NB];
__device__ int   g_bpre[SCAN_NB];
__device__ int2  g_edge[EE];                  // .x = col, .y = val bits

// ---------------- helpers ----------------
__device__ __forceinline__ uint32_t f2tf32(float f) {
    uint32_t r;
    asm("cvt.rna.tf32.f32 %0, %1;" : "=r"(r) : "f"(f));
    return r;
}

__device__ __forceinline__ void mma_tf32(float* c, const uint32_t* a, uint32_t b0, uint32_t b1) {
    asm volatile(
        "mma.sync.aligned.m16n8k8.row.col.f32.tf32.tf32.f32 "
        "{%0,%1,%2,%3}, {%4,%5,%6,%7}, {%8,%9}, {%0,%1,%2,%3};"
        : "+f"(c[0]), "+f"(c[1]), "+f"(c[2]), "+f"(c[3])
        : "r"(a[0]), "r"(a[1]), "r"(a[2]), "r"(a[3]), "r"(b0), "r"(b1));
}

// ---------------- GEMM: feat = (emb*mask1) @ W^T + b_fc  (tf32 mma.sync) -------
#define KB 32
#define KPAD (KB + 4)

__global__ __launch_bounds__(256) void gemm_mma_kernel(
    const float* __restrict__ emb, const float* __restrict__ mask1,
    const float* __restrict__ W, const float* __restrict__ b_fc)
{
    __shared__ uint32_t as[128][KPAD];   // A tile (tf32 bits), rows x k
    __shared__ uint32_t bs[128][KPAD];   // B tile = W rows (output cols) x k

    const int tid   = threadIdx.x;
    const int wid   = tid >> 5;
    const int lane  = tid & 31;
    const int warpM = wid >> 1;          // 0..3
    const int warpN = wid & 1;           // 0..1
    const int grp   = lane >> 2;         // 0..7
    const int tig   = lane & 3;          // 0..3
    const int row0  = blockIdx.x * 128;

    float acc[2][8][4];
#pragma unroll
    for (int mt = 0; mt < 2; mt++)
#pragma unroll
        for (int nt = 0; nt < 8; nt++)
#pragma unroll
            for (int j = 0; j < 4; j++) acc[mt][nt][j] = 0.f;

    for (int kc = 0; kc < CIN; kc += KB) {
        // --- stage A: (emb*mask1) -> tf32, 128 rows x 32 k ---
#pragma unroll
        for (int i = 0; i < 4; i++) {
            const int idx = i * 256 + tid;       // float4 index, 0..1023
            const int row = idx >> 3;            // 0..127
            const int kq  = (idx & 7) * 4;       // 0..28
            const int grow = row0 + row;
            float4 e = make_float4(0.f, 0.f, 0.f, 0.f);
            if (grow < NN) {
                const float4 a4 = *(const float4*)&emb  [(size_t)grow * CIN + kc + kq];
                const float4 m4 = *(const float4*)&mask1[(size_t)grow * CIN + kc + kq];
                e.x = a4.x * m4.x; e.y = a4.y * m4.y;
                e.z = a4.z * m4.z; e.w = a4.w * m4.w;
            }
            uint4 t;
            t.x = f2tf32(e.x); t.y = f2tf32(e.y); t.z = f2tf32(e.z); t.w = f2tf32(e.w);
            *(uint4*)&as[row][kq] = t;
        }
        // --- stage B: W (COUT x CIN, K-major) -> tf32 ---
#pragma unroll
        for (int i = 0; i < 4; i++) {
            const int idx = i * 256 + tid;
            const int row = idx >> 3;            // output col
            const int kq  = (idx & 7) * 4;
            const float4 w4 = *(const float4*)&W[(size_t)row * CIN + kc + kq];
            uint4 t;
            t.x = f2tf32(w4.x); t.y = f2tf32(w4.y); t.z = f2tf32(w4.z); t.w = f2tf32(w4.w);
            *(uint4*)&bs[row][kq] = t;
        }
        __syncthreads();

        // --- compute: 4 k8-steps ---
#pragma unroll
        for (int ks = 0; ks < 4; ks++) {
            const int k0 = ks * 8;
            uint32_t afr[2][4];
#pragma unroll
            for (int mt = 0; mt < 2; mt++) {
                const int r = warpM * 32 + mt * 16 + grp;
                afr[mt][0] = as[r][k0 + tig];
                afr[mt][1] = as[r + 8][k0 + tig];
                afr[mt][2] = as[r][k0 + tig + 4];
                afr[mt][3] = as[r + 8][k0 + tig + 4];
            }
#pragma unroll
            for (int nt = 0; nt < 8; nt++) {
                const int c = warpN * 64 + nt * 8 + grp;
                const uint32_t b0 = bs[c][k0 + tig];
                const uint32_t b1 = bs[c][k0 + tig + 4];
                mma_tf32(acc[0][nt], afr[0], b0, b1);
                mma_tf32(acc[1][nt], afr[1], b0, b1);
            }
        }
        __syncthreads();
    }

    // --- epilogue: +b_fc, convert to fp16, store feat ---
#pragma unroll
    for (int mt = 0; mt < 2; mt++) {
        const int r0 = row0 + warpM * 32 + mt * 16 + grp;
        const int r1 = r0 + 8;
#pragma unroll
        for (int nt = 0; nt < 8; nt++) {
            const int col = warpN * 64 + nt * 8 + 2 * tig;
            const float2 bf = *(const float2*)&b_fc[col];
            if (r0 < NN) {
                const __half2 h = __float22half2_rn(
                    make_float2(acc[mt][nt][0] + bf.x, acc[mt][nt][1] + bf.y));
                *(__half2*)&g_feat[(size_t)r0 * COUT + col] = h;
            }
            if (r1 < NN) {
                const __half2 h = __float22half2_rn(
                    make_float2(acc[mt][nt][2] + bf.x, acc[mt][nt][3] + bf.y));
                *(__half2*)&g_feat[(size_t)r1 * COUT + col] = h;
            }
        }
    }
}

// ---------------- CSR construction ----------------
__global__ void zero_counts_kernel() {
    int i = blockIdx.x * blockDim.x + threadIdx.x;
    if (i < NN) g_count[i] = 0;
}

__global__ void hist_kernel(const int* __restrict__ rows) {
    int e = blockIdx.x * blockDim.x + threadIdx.x;
    if (e < EE) atomicAdd(&g_count[rows[e]], 1);
}

__global__ __launch_bounds__(SCAN_B) void scan1_kernel() {
    __shared__ int s[SCAN_B];
    const int t = threadIdx.x;
    const int b = blockIdx.x;
    const int idx = b * SCAN_B + t;
    const int v = (idx < NN) ? g_count[idx] : 0;
    s[t] = v;
    __syncthreads();
#pragma unroll
    for (int off = 1; off < SCAN_B; off <<= 1) {
        int u = 0;
        if (t >= off) u = s[t - off];
        __syncthreads();
        if (t >= off) s[t] += u;
        __syncthreads();
    }
    if (idx < NN) g_off[idx] = s[t] - v;
    if (t == SCAN_B - 1) g_bsum[b] = s[t];
}

__global__ __launch_bounds__(128) void scan2_kernel() {
    __shared__ int s[128];
    const int t = threadIdx.x;
    const int v = (t < SCAN_NB) ? g_bsum[t] : 0;
    s[t] = v;
    __syncthreads();
#pragma unroll
    for (int off = 1; off < 128; off <<= 1) {
        int u = 0;
        if (t >= off) u = s[t - off];
        __syncthreads();
        if (t >= off) s[t] += u;
        __syncthreads();
    }
    if (t < SCAN_NB) g_bpre[t] = s[t] - v;
}

__global__ __launch_bounds__(SCAN_B) void scan3_kernel() {
    const int b = blockIdx.x;
    const int idx = b * SCAN_B + threadIdx.x;
    if (idx < NN) {
        const int o = g_off[idx] + g_bpre[b];
        g_off[idx] = o;
        g_cur[idx] = o;
    }
    if (idx == 0) g_off[NN] = EE;
}

__global__ void scatter_kernel(const int* __restrict__ rows,
                               const int* __restrict__ cols,
                               const float* __restrict__ vals) {
    int e = blockIdx.x * blockDim.x + threadIdx.x;
    if (e < EE) {
        int r = rows[e];
        int p = atomicAdd(&g_cur[r], 1);
        g_edge[p] = make_int2(cols[e], __float_as_int(vals[e]));
    }
}

// ---------------- SpMM: warp per (row, col-half), prefetch-8 ----------------
// Each warp unit handles 64 fp16 columns of one row; lane owns 2 cols (4 B).
__global__ __launch_bounds__(256) void spmm_kernel(
    const float* __restrict__ bias, const float* __restrict__ mask2,
    const float* __restrict__ prelu_a, float* __restrict__ out)
{
    const int wu = blockIdx.x * 8 + (threadIdx.x >> 5);   // 0 .. 2*NN-1
    if (wu >= 2 * NN) return;
    const int row  = wu >> 1;
    const int half = wu & 1;
    const int lane = threadIdx.x & 31;

    const int start = g_off[row];
    const int end   = g_off[row + 1];

    // lane's 2 cols as one uint (half2); feat row = 64 uints
    const uint32_t* __restrict__ fbase =
        (const uint32_t*)g_feat + half * 32 + lane;

    float2 acc0 = make_float2(0.f, 0.f);
    float2 acc1 = make_float2(0.f, 0.f);

    for (int e0 = start; e0 < end; e0 += 32) {
        const int n = min(32, end - e0);
        int   c = 0;
        float v = 0.f;
        if (lane < n) {
            const int2 ed = g_edge[e0 + lane];
            c = ed.x;
            v = __int_as_float(ed.y);
        }
        for (int g0 = 0; g0 < n; g0 += 8) {
            const int gn = min(8, n - g0);
            uint32_t buf[8];
            float    vv[8];
            // issue up to 8 independent gathers
#pragma unroll
            for (int t = 0; t < 8; t++) {
                if (t < gn) {
                    const int   cj = __shfl_sync(0xffffffffu, c, g0 + t);
                    vv[t]  = __shfl_sync(0xffffffffu, v, g0 + t);
                    buf[t] = __ldg(fbase + (size_t)cj * 64);
                }
            }
            // consume (even/odd accumulator split breaks FFMA chains)
#pragma unroll
            for (int t = 0; t < 8; t++) {
                if (t < gn) {
                    const float2 f = __half22float2(*(const __half2*)&buf[t]);
                    if (t & 1) {
                        acc1.x = fmaf(vv[t], f.x, acc1.x);
                        acc1.y = fmaf(vv[t], f.y, acc1.y);
                    } else {
                        acc0.x = fmaf(vv[t], f.x, acc0.x);
                        acc0.y = fmaf(vv[t], f.y, acc0.y);
                    }
                }
            }
        }
    }

    const float2 accf = make_float2(acc0.x + acc1.x, acc0.y + acc1.y);

    const int colb = half * 64 + lane * 2;
    const float2 b = *(const float2*)&bias[colb];
    const float2 m = *(const float2*)&mask2[(size_t)row * COUT + colb];
    const float  a = prelu_a[0];

    float2 o;
    o.x = (accf.x + b.x) * m.x;
    o.y = (accf.y + b.y) * m.y;
    o.x = o.x > 0.f ? o.x : a * o.x;
    o.y = o.y > 0.f ? o.y : a * o.y;

    *(float2*)&out[(size_t)row * COUT + colb] = o;
}

// ---------------- launch (fork-join: CSR build overlaps GEMM) ----------------
static cudaStream_t s_side = nullptr;
static cudaEvent_t  s_evFork = nullptr;
static cudaEvent_t  s_evJoin = nullptr;

extern "C" void kernel_launch(void* const* d_in, const int* in_sizes, int n_in,
                              void* d_out, int out_size)
{
    const float* emb     = (const float*)d_in[0];
    const float* vals    = (const float*)d_in[1];
    const float* W       = (const float*)d_in[2];
    const float* b_fc    = (const float*)d_in[3];
    const float* bias    = (const float*)d_in[4];
    const float* prelu_a = (const float*)d_in[5];
    const float* mask1   = (const float*)d_in[6];
    const float* mask2   = (const float*)d_in[7];
    const int*   rows    = (const int*)d_in[8];
    const int*   cols    = (const int*)d_in[9];
    float*       out     = (float*)d_out;

    if (s_side == nullptr) {   // host-side infra init (first, uncaptured call)
        cudaStreamCreateWithFlags(&s_side, cudaStreamNonBlocking);
        cudaEventCreateWithFlags(&s_evFork, cudaEventDisableTiming);
        cudaEventCreateWithFlags(&s_evJoin, cudaEventDisableTiming);
    }

    // Fork side stream off the (captured) legacy stream
    cudaEventRecord(s_evFork, 0);
    cudaStreamWaitEvent(s_side, s_evFork, 0);

    // Branch A (legacy stream): GEMM via tf32 mma.sync
    gemm_mma_kernel<<<(NN + 127) / 128, 256>>>(emb, mask1, W, b_fc);

    // Branch B (side stream): CSR build
    zero_counts_kernel<<<(NN + 255) / 256, 256, 0, s_side>>>();
    hist_kernel<<<(EE + 255) / 256, 256, 0, s_side>>>(rows);
    scan1_kernel<<<SCAN_NB, SCAN_B, 0, s_side>>>();
    scan2_kernel<<<1, 128, 0, s_side>>>();
    scan3_kernel<<<SCAN_NB, SCAN_B, 0, s_side>>>();
    scatter_kernel<<<(EE + 255) / 256, 256, 0, s_side>>>(rows, cols, vals);

    // Join
    cudaEventRecord(s_evJoin, s_side);
    cudaStreamWaitEvent(0, s_evJoin, 0);

    // SpMM + epilogue: one warp per (row, col-half)
    spmm_kernel<<<(2 * NN + 7) / 8, 256>>>(bias, mask2, prelu_a, out);
}

// round 8
// speedup vs baseline: 1.3893x; 1.3893x over previous
#include <cuda_runtime.h>
#include <cuda_fp16.h>
#include <cstdint>

#define NN   100000
#define EE   1600000
#define CIN  256
#define COUT 128

#define SCAN_B 1024
#define SCAN_NB ((NN + SCAN_B - 1) / SCAN_B)   // 98

// ---------------- scratch (static device globals; no allocation) ----------------
__device__ __half g_feat[(size_t)NN * COUT];  // 25.6 MB -> L2-resident
__device__ int   g_count[NN];
__device__ int   g_off[NN + 1];
__device__ int   g_cur[NN];
__device__ int   g_bsum[SCAN_NB];
__device__ int   g_bpre[SCAN_NB];
__device__ int2  g_edge[EE];                  // .x = col, .y = val bits

// ---------------- helpers ----------------
__device__ __forceinline__ uint32_t f2tf32(float f) {
    uint32_t r;
    asm("cvt.rna.tf32.f32 %0, %1;" : "=r"(r) : "f"(f));
    return r;
}

__device__ __forceinline__ void mma_tf32(float* c, const uint32_t* a, uint32_t b0, uint32_t b1) {
    asm volatile(
        "mma.sync.aligned.m16n8k8.row.col.f32.tf32.tf32.f32 "
        "{%0,%1,%2,%3}, {%4,%5,%6,%7}, {%8,%9}, {%0,%1,%2,%3};"
        : "+f"(c[0]), "+f"(c[1]), "+f"(c[2]), "+f"(c[3])
        : "r"(a[0]), "r"(a[1]), "r"(a[2]), "r"(a[3]), "r"(b0), "r"(b1));
}

// ---------------- GEMM: feat = (emb*mask1) @ W^T + b_fc  (tf32 mma.sync) -------
#define KB 32
#define KPAD (KB + 4)

__global__ __launch_bounds__(256) void gemm_mma_kernel(
    const float* __restrict__ emb, const float* __restrict__ mask1,
    const float* __restrict__ W, const float* __restrict__ b_fc)
{
    __shared__ uint32_t as[128][KPAD];   // A tile (tf32 bits), rows x k
    __shared__ uint32_t bs[128][KPAD];   // B tile = W rows (output cols) x k

    const int tid   = threadIdx.x;
    const int wid   = tid >> 5;
    const int lane  = tid & 31;
    const int warpM = wid >> 1;          // 0..3
    const int warpN = wid & 1;           // 0..1
    const int grp   = lane >> 2;         // 0..7
    const int tig   = lane & 3;          // 0..3
    const int row0  = blockIdx.x * 128;

    float acc[2][8][4];
#pragma unroll
    for (int mt = 0; mt < 2; mt++)
#pragma unroll
        for (int nt = 0; nt < 8; nt++)
#pragma unroll
            for (int j = 0; j < 4; j++) acc[mt][nt][j] = 0.f;

    for (int kc = 0; kc < CIN; kc += KB) {
        // --- stage A: (emb*mask1) -> tf32, 128 rows x 32 k ---
#pragma unroll
        for (int i = 0; i < 4; i++) {
            const int idx = i * 256 + tid;       // float4 index, 0..1023
            const int row = idx >> 3;            // 0..127
            const int kq  = (idx & 7) * 4;       // 0..28
            const int grow = row0 + row;
            float4 e = make_float4(0.f, 0.f, 0.f, 0.f);
            if (grow < NN) {
                const float4 a4 = *(const float4*)&emb  [(size_t)grow * CIN + kc + kq];
                const float4 m4 = *(const float4*)&mask1[(size_t)grow * CIN + kc + kq];
                e.x = a4.x * m4.x; e.y = a4.y * m4.y;
                e.z = a4.z * m4.z; e.w = a4.w * m4.w;
            }
            uint4 t;
            t.x = f2tf32(e.x); t.y = f2tf32(e.y); t.z = f2tf32(e.z); t.w = f2tf32(e.w);
            *(uint4*)&as[row][kq] = t;
        }
        // --- stage B: W (COUT x CIN, K-major) -> tf32 ---
#pragma unroll
        for (int i = 0; i < 4; i++) {
            const int idx = i * 256 + tid;
            const int row = idx >> 3;            // output col
            const int kq  = (idx & 7) * 4;
            const float4 w4 = *(const float4*)&W[(size_t)row * CIN + kc + kq];
            uint4 t;
            t.x = f2tf32(w4.x); t.y = f2tf32(w4.y); t.z = f2tf32(w4.z); t.w = f2tf32(w4.w);
            *(uint4*)&bs[row][kq] = t;
        }
        __syncthreads();

        // --- compute: 4 k8-steps ---
#pragma unroll
        for (int ks = 0; ks < 4; ks++) {
            const int k0 = ks * 8;
            uint32_t afr[2][4];
#pragma unroll
            for (int mt = 0; mt < 2; mt++) {
                const int r = warpM * 32 + mt * 16 + grp;
                afr[mt][0] = as[r][k0 + tig];
                afr[mt][1] = as[r + 8][k0 + tig];
                afr[mt][2] = as[r][k0 + tig + 4];
                afr[mt][3] = as[r + 8][k0 + tig + 4];
            }
#pragma unroll
            for (int nt = 0; nt < 8; nt++) {
                const int c = warpN * 64 + nt * 8 + grp;
                const uint32_t b0 = bs[c][k0 + tig];
                const uint32_t b1 = bs[c][k0 + tig + 4];
                mma_tf32(acc[0][nt], afr[0], b0, b1);
                mma_tf32(acc[1][nt], afr[1], b0, b1);
            }
        }
        __syncthreads();
    }

    // --- epilogue: +b_fc, convert to fp16, store feat ---
#pragma unroll
    for (int mt = 0; mt < 2; mt++) {
        const int r0 = row0 + warpM * 32 + mt * 16 + grp;
        const int r1 = r0 + 8;
#pragma unroll
        for (int nt = 0; nt < 8; nt++) {
            const int col = warpN * 64 + nt * 8 + 2 * tig;
            const float2 bf = *(const float2*)&b_fc[col];
            if (r0 < NN) {
                const __half2 h = __float22half2_rn(
                    make_float2(acc[mt][nt][0] + bf.x, acc[mt][nt][1] + bf.y));
                *(__half2*)&g_feat[(size_t)r0 * COUT + col] = h;
            }
            if (r1 < NN) {
                const __half2 h = __float22half2_rn(
                    make_float2(acc[mt][nt][2] + bf.x, acc[mt][nt][3] + bf.y));
                *(__half2*)&g_feat[(size_t)r1 * COUT + col] = h;
            }
        }
    }
}

// ---------------- CSR construction ----------------
__global__ void zero_counts_kernel() {
    int i = blockIdx.x * blockDim.x + threadIdx.x;
    if (i < NN) g_count[i] = 0;
}

__global__ void hist_kernel(const int* __restrict__ rows) {
    int e = blockIdx.x * blockDim.x + threadIdx.x;
    if (e < EE) atomicAdd(&g_count[rows[e]], 1);
}

__global__ __launch_bounds__(SCAN_B) void scan1_kernel() {
    __shared__ int s[SCAN_B];
    const int t = threadIdx.x;
    const int b = blockIdx.x;
    const int idx = b * SCAN_B + t;
    const int v = (idx < NN) ? g_count[idx] : 0;
    s[t] = v;
    __syncthreads();
#pragma unroll
    for (int off = 1; off < SCAN_B; off <<= 1) {
        int u = 0;
        if (t >= off) u = s[t - off];
        __syncthreads();
        if (t >= off) s[t] += u;
        __syncthreads();
    }
    if (idx < NN) g_off[idx] = s[t] - v;
    if (t == SCAN_B - 1) g_bsum[b] = s[t];
}

__global__ __launch_bounds__(128) void scan2_kernel() {
    __shared__ int s[128];
    const int t = threadIdx.x;
    const int v = (t < SCAN_NB) ? g_bsum[t] : 0;
    s[t] = v;
    __syncthreads();
#pragma unroll
    for (int off = 1; off < 128; off <<= 1) {
        int u = 0;
        if (t >= off) u = s[t - off];
        __syncthreads();
        if (t >= off) s[t] += u;
        __syncthreads();
    }
    if (t < SCAN_NB) g_bpre[t] = s[t] - v;
}

__global__ __launch_bounds__(SCAN_B) void scan3_kernel() {
    const int b = blockIdx.x;
    const int idx = b * SCAN_B + threadIdx.x;
    if (idx < NN) {
        const int o = g_off[idx] + g_bpre[b];
        g_off[idx] = o;
        g_cur[idx] = o;
    }
    if (idx == 0) g_off[NN] = EE;
}

__global__ void scatter_kernel(const int* __restrict__ rows,
                               const int* __restrict__ cols,
                               const float* __restrict__ vals) {
    int e = blockIdx.x * blockDim.x + threadIdx.x;
    if (e < EE) {
        int r = rows[e];
        int p = atomicAdd(&g_cur[r], 1);
        g_edge[p] = make_int2(cols[e], __float_as_int(vals[e]));
    }
}

// ---------------- warp-per-row SpMM (fp16 gather) + fused epilogue ----------------
__global__ __launch_bounds__(256) void spmm_kernel(
    const float* __restrict__ bias, const float* __restrict__ mask2,
    const float* __restrict__ prelu_a, float* __restrict__ out)
{
    const int warp = blockIdx.x * 8 + (threadIdx.x >> 5);
    if (warp >= NN) return;
    const int lane = threadIdx.x & 31;

    // hoist epilogue operands: latency hides under the gather loop
    const float4 b = ((const float4*)bias)[lane];
    const float4 m = ((const float4*)mask2)[(size_t)warp * 32 + lane];
    const float  a = prelu_a[0];

    const int start = g_off[warp];
    const int end   = g_off[warp + 1];

    const uint2* __restrict__ fbase = (const uint2*)g_feat + lane;  // row = 32 uint2

    float4 acc0 = make_float4(0.f, 0.f, 0.f, 0.f);
    float4 acc1 = make_float4(0.f, 0.f, 0.f, 0.f);

    int e0 = start;
    // --- main path: full 32-edge groups, predicate-free ---
    for (; e0 + 32 <= end; e0 += 32) {
        const int2 ed = g_edge[e0 + lane];
        const int   c = ed.x;
        const float v = __int_as_float(ed.y);
#pragma unroll
        for (int g = 0; g < 8; g++) {
            uint2 buf[4];
            float vv[4];
#pragma unroll
            for (int t = 0; t < 4; t++) {
                const int j = g * 4 + t;
                const int cj = __shfl_sync(0xffffffffu, c, j);
                vv[t] = __shfl_sync(0xffffffffu, v, j);
                buf[t] = fbase[(size_t)cj * 32];
            }
#pragma unroll
            for (int t = 0; t < 4; t++) {
                const float2 f0 = __half22float2(*(const __half2*)&buf[t].x);
                const float2 f1 = __half22float2(*(const __half2*)&buf[t].y);
                float4& ac = (t & 1) ? acc1 : acc0;
                ac.x = fmaf(vv[t], f0.x, ac.x);
                ac.y = fmaf(vv[t], f0.y, ac.y);
                ac.z = fmaf(vv[t], f1.x, ac.z);
                ac.w = fmaf(vv[t], f1.y, ac.w);
            }
        }
    }
    // --- tail: <32 edges ---
    if (e0 < end) {
        const int n = end - e0;
        int   c = 0;
        float v = 0.f;
        if (lane < n) {
            const int2 ed = g_edge[e0 + lane];
            c = ed.x;
            v = __int_as_float(ed.y);
        }
#pragma unroll 4
        for (int j = 0; j < n; j++) {
            const int   cj = __shfl_sync(0xffffffffu, c, j);
            const float vj = __shfl_sync(0xffffffffu, v, j);
            const uint2 hv = fbase[(size_t)cj * 32];
            const float2 f0 = __half22float2(*(const __half2*)&hv.x);
            const float2 f1 = __half22float2(*(const __half2*)&hv.y);
            acc0.x = fmaf(vj, f0.x, acc0.x);
            acc0.y = fmaf(vj, f0.y, acc0.y);
            acc0.z = fmaf(vj, f1.x, acc0.z);
            acc0.w = fmaf(vj, f1.y, acc0.w);
        }
    }

    float4 o;
    o.x = (acc0.x + acc1.x + b.x) * m.x;
    o.y = (acc0.y + acc1.y + b.y) * m.y;
    o.z = (acc0.z + acc1.z + b.z) * m.z;
    o.w = (acc0.w + acc1.w + b.w) * m.w;
    o.x = o.x > 0.f ? o.x : a * o.x;
    o.y = o.y > 0.f ? o.y : a * o.y;
    o.z = o.z > 0.f ? o.z : a * o.z;
    o.w = o.w > 0.f ? o.w : a * o.w;

    ((float4*)out)[(size_t)warp * 32 + lane] = o;
}

// ---------------- launch (fork-join: CSR build overlaps GEMM) ----------------
static cudaStream_t s_side = nullptr;
static cudaEvent_t  s_evFork = nullptr;
static cudaEvent_t  s_evJoin = nullptr;

extern "C" void kernel_launch(void* const* d_in, const int* in_sizes, int n_in,
                              void* d_out, int out_size)
{
    const float* emb     = (const float*)d_in[0];
    const float* vals    = (const float*)d_in[1];
    const float* W       = (const float*)d_in[2];
    const float* b_fc    = (const float*)d_in[3];
    const float* bias    = (const float*)d_in[4];
    const float* prelu_a = (const float*)d_in[5];
    const float* mask1   = (const float*)d_in[6];
    const float* mask2   = (const float*)d_in[7];
    const int*   rows    = (const int*)d_in[8];
    const int*   cols    = (const int*)d_in[9];
    float*       out     = (float*)d_out;

    if (s_side == nullptr) {   // host-side infra init (first, uncaptured call)
        cudaStreamCreateWithFlags(&s_side, cudaStreamNonBlocking);
        cudaEventCreateWithFlags(&s_evFork, cudaEventDisableTiming);
        cudaEventCreateWithFlags(&s_evJoin, cudaEventDisableTiming);
    }

    // Fork side stream off the (captured) legacy stream
    cudaEventRecord(s_evFork, 0);
    cudaStreamWaitEvent(s_side, s_evFork, 0);

    // Branch A (legacy stream): GEMM via tf32 mma.sync
    gemm_mma_kernel<<<(NN + 127) / 128, 256>>>(emb, mask1, W, b_fc);

    // Branch B (side stream): CSR build
    zero_counts_kernel<<<(NN + 255) / 256, 256, 0, s_side>>>();
    hist_kernel<<<(EE + 255) / 256, 256, 0, s_side>>>(rows);
    scan1_kernel<<<SCAN_NB, SCAN_B, 0, s_side>>>();
    scan2_kernel<<<1, 128, 0, s_side>>>();
    scan3_kernel<<<SCAN_NB, SCAN_B, 0, s_side>>>();
    scatter_kernel<<<(EE + 255) / 256, 256, 0, s_side>>>(rows, cols, vals);

    // Join
    cudaEventRecord(s_evJoin, s_side);
    cudaStreamWaitEvent(0, s_evJoin, 0);

    // SpMM + epilogue (warp per row)
    spmm_kernel<<<(NN + 7) / 8, 256>>>(bias, mask2, prelu_a, out);
}

// round 9
// speedup vs baseline: 1.5929x; 1.1465x over previous
#include <cuda_runtime.h>
#include <cuda_fp16.h>
#include <cstdint>

#define NN   100000
#define EE   1600000
#define CIN  256
#define COUT 128

#define SCAN_B 1024
#define SCAN_NB ((NN + SCAN_B - 1) / SCAN_B)   // 98

// ---------------- scratch (static device globals; no allocation) ----------------
__device__ __half g_feat[(size_t)NN * COUT];  // 25.6 MB -> L2-resident
__device__ int   g_count[NN];                 // zeroed at load; re-zeroed by finalize
__device__ int   g_off[NN + 1];
__device__ int   g_cur[NN];
__device__ int   g_bsum[SCAN_NB];
__device__ int   g_bpre[SCAN_NB];
__device__ unsigned g_ticket;                 // zeroed at load; reset by last block
__device__ int2  g_edge[EE];                  // .x = col, .y = val bits

// ---------------- helpers ----------------
__device__ __forceinline__ uint32_t f2tf32(float f) {
    uint32_t r;
    asm("cvt.rna.tf32.f32 %0, %1;" : "=r"(r) : "f"(f));
    return r;
}

__device__ __forceinline__ void mma_tf32(float* c, const uint32_t* a, uint32_t b0, uint32_t b1) {
    asm volatile(
        "mma.sync.aligned.m16n8k8.row.col.f32.tf32.tf32.f32 "
        "{%0,%1,%2,%3}, {%4,%5,%6,%7}, {%8,%9}, {%0,%1,%2,%3};"
        : "+f"(c[0]), "+f"(c[1]), "+f"(c[2]), "+f"(c[3])
        : "r"(a[0]), "r"(a[1]), "r"(a[2]), "r"(a[3]), "r"(b0), "r"(b1));
}

// ---------------- GEMM: feat = (emb*mask1) @ W^T + b_fc  (tf32 mma.sync) -------
// A-stream (emb, mask1) register-prefetched one chunk ahead to hide DRAM latency.
#define KB 32
#define KPAD (KB + 4)
#define NCH (CIN / KB)   // 8

__global__ __launch_bounds__(256) void gemm_mma_kernel(
    const float* __restrict__ emb, const float* __restrict__ mask1,
    const float* __restrict__ W, const float* __restrict__ b_fc)
{
    __shared__ uint32_t as[128][KPAD];   // A tile (tf32 bits), rows x k
    __shared__ uint32_t bs[128][KPAD];   // B tile = W rows (output cols) x k

    const int tid   = threadIdx.x;
    const int wid   = tid >> 5;
    const int lane  = tid & 31;
    const int warpM = wid >> 1;          // 0..3
    const int warpN = wid & 1;           // 0..1
    const int grp   = lane >> 2;         // 0..7
    const int tig   = lane & 3;          // 0..3
    const int row0  = blockIdx.x * 128;

    // per-thread A staging coordinates (fixed across chunks)
    int arow[4], akq[4];
    bool aok[4];
#pragma unroll
    for (int i = 0; i < 4; i++) {
        const int idx = i * 256 + tid;       // float4 index, 0..1023
        arow[i] = idx >> 3;                  // 0..127
        akq[i]  = (idx & 7) * 4;             // 0..28
        aok[i]  = (row0 + arow[i]) < NN;
    }

    float acc[2][8][4];
#pragma unroll
    for (int mt = 0; mt < 2; mt++)
#pragma unroll
        for (int nt = 0; nt < 8; nt++)
#pragma unroll
            for (int j = 0; j < 4; j++) acc[mt][nt][j] = 0.f;

    // --- preload chunk 0 of A-stream ---
    float4 pe[4], pm[4];
#pragma unroll
    for (int i = 0; i < 4; i++) {
        if (aok[i]) {
            pe[i] = *(const float4*)&emb  [(size_t)(row0 + arow[i]) * CIN + akq[i]];
            pm[i] = *(const float4*)&mask1[(size_t)(row0 + arow[i]) * CIN + akq[i]];
        } else {
            pe[i] = make_float4(0.f, 0.f, 0.f, 0.f);
            pm[i] = make_float4(0.f, 0.f, 0.f, 0.f);
        }
    }

    for (int ch = 0; ch < NCH; ch++) {
        const int kc = ch * KB;

        // --- STS A from prefetched registers ---
#pragma unroll
        for (int i = 0; i < 4; i++) {
            uint4 t;
            t.x = f2tf32(pe[i].x * pm[i].x);
            t.y = f2tf32(pe[i].y * pm[i].y);
            t.z = f2tf32(pe[i].z * pm[i].z);
            t.w = f2tf32(pe[i].w * pm[i].w);
            *(uint4*)&as[arow[i]][akq[i]] = t;
        }
        // --- stage B: W (COUT x CIN, K-major) -> tf32 (L2-resident stream) ---
#pragma unroll
        for (int i = 0; i < 4; i++) {
            const float4 w4 = *(const float4*)&W[(size_t)arow[i] * CIN + kc + akq[i]];
            uint4 t;
            t.x = f2tf32(w4.x); t.y = f2tf32(w4.y); t.z = f2tf32(w4.z); t.w = f2tf32(w4.w);
            *(uint4*)&bs[arow[i]][kc ? akq[i] : akq[i]] = t;   // same kq slot
        }
        __syncthreads();

        // --- prefetch next chunk of A (latency hides under MMA below) ---
        if (ch + 1 < NCH) {
            const int kn = kc + KB;
#pragma unroll
            for (int i = 0; i < 4; i++) {
                if (aok[i]) {
                    pe[i] = *(const float4*)&emb  [(size_t)(row0 + arow[i]) * CIN + kn + akq[i]];
                    pm[i] = *(const float4*)&mask1[(size_t)(row0 + arow[i]) * CIN + kn + akq[i]];
                }
            }
        }

        // --- compute: 4 k8-steps ---
#pragma unroll
        for (int ks = 0; ks < 4; ks++) {
            const int k0 = ks * 8;
            uint32_t afr[2][4];
#pragma unroll
            for (int mt = 0; mt < 2; mt++) {
                const int r = warpM * 32 + mt * 16 + grp;
                afr[mt][0] = as[r][k0 + tig];
                afr[mt][1] = as[r + 8][k0 + tig];
                afr[mt][2] = as[r][k0 + tig + 4];
                afr[mt][3] = as[r + 8][k0 + tig + 4];
            }
#pragma unroll
            for (int nt = 0; nt < 8; nt++) {
                const int c = warpN * 64 + nt * 8 + grp;
                const uint32_t b0 = bs[c][k0 + tig];
                const uint32_t b1 = bs[c][k0 + tig + 4];
                mma_tf32(acc[0][nt], afr[0], b0, b1);
                mma_tf32(acc[1][nt], afr[1], b0, b1);
            }
        }
        __syncthreads();
    }

    // --- epilogue: +b_fc, convert to fp16, store feat ---
#pragma unroll
    for (int mt = 0; mt < 2; mt++) {
        const int r0 = row0 + warpM * 32 + mt * 16 + grp;
        const int r1 = r0 + 8;
#pragma unroll
        for (int nt = 0; nt < 8; nt++) {
            const int col = warpN * 64 + nt * 8 + 2 * tig;
            const float2 bf = *(const float2*)&b_fc[col];
            if (r0 < NN) {
                const __half2 h = __float22half2_rn(
                    make_float2(acc[mt][nt][0] + bf.x, acc[mt][nt][1] + bf.y));
                *(__half2*)&g_feat[(size_t)r0 * COUT + col] = h;
            }
            if (r1 < NN) {
                const __half2 h = __float22half2_rn(
                    make_float2(acc[mt][nt][2] + bf.x, acc[mt][nt][3] + bf.y));
                *(__half2*)&g_feat[(size_t)r1 * COUT + col] = h;
            }
        }
    }
}

// ---------------- CSR construction ----------------
__global__ void hist_kernel(const int* __restrict__ rows) {
    int e = blockIdx.x * blockDim.x + threadIdx.x;
    if (e < EE) atomicAdd(&g_count[rows[e]], 1);
}

// Per-block scan + last-block scans the block sums (fused scan1+scan2)
__global__ __launch_bounds__(SCAN_B) void scanA_kernel() {
    __shared__ int s[SCAN_B];
    __shared__ int s2[128];
    __shared__ int lastFlag;
    const int t = threadIdx.x;
    const int b = blockIdx.x;
    const int idx = b * SCAN_B + t;
    const int v = (idx < NN) ? g_count[idx] : 0;
    s[t] = v;
    __syncthreads();
#pragma unroll
    for (int off = 1; off < SCAN_B; off <<= 1) {
        int u = 0;
        if (t >= off) u = s[t - off];
        __syncthreads();
        if (t >= off) s[t] += u;
        __syncthreads();
    }
    if (idx < NN) g_off[idx] = s[t] - v;        // local exclusive prefix
    if (t == SCAN_B - 1) g_bsum[b] = s[t];      // block total
    __syncthreads();
    if (t == 0) {
        __threadfence();
        lastFlag = (atomicAdd(&g_ticket, 1u) == (unsigned)(gridDim.x - 1));
    }
    __syncthreads();
    if (!lastFlag) return;

    // last block: exclusive scan of the 98 block sums
    const int v2 = (t < SCAN_NB) ? g_bsum[t] : 0;
    if (t < 128) s2[t] = v2;
    __syncthreads();
#pragma unroll
    for (int off = 1; off < 128; off <<= 1) {
        int u = 0;
        if (t < 128 && t >= off) u = s2[t - off];
        __syncthreads();
        if (t < 128 && t >= off) s2[t] += u;
        __syncthreads();
    }
    if (t < SCAN_NB) g_bpre[t] = s2[t] - v2;
    if (t == 0) g_ticket = 0;                   // reset for next replay
}

// add block prefixes, init cursors, zero counts for next replay, sentinel
__global__ __launch_bounds__(SCAN_B) void finalize_kernel() {
    const int b = blockIdx.x;
    const int idx = b * SCAN_B + threadIdx.x;
    if (idx < NN) {
        const int o = g_off[idx] + g_bpre[b];
        g_off[idx] = o;
        g_cur[idx] = o;
        g_count[idx] = 0;
    }
    if (idx == 0) g_off[NN] = EE;
}

__global__ void scatter_kernel(const int* __restrict__ rows,
                               const int* __restrict__ cols,
                               const float* __restrict__ vals) {
    int e = blockIdx.x * blockDim.x + threadIdx.x;
    if (e < EE) {
        int r = rows[e];
        int p = atomicAdd(&g_cur[r], 1);
        g_edge[p] = make_int2(cols[e], __float_as_int(vals[e]));
    }
}

// ---------------- warp-per-row SpMM (exact R6 form — frozen) ----------------
__global__ __launch_bounds__(256) void spmm_kernel(
    const float* __restrict__ bias, const float* __restrict__ mask2,
    const float* __restrict__ prelu_a, float* __restrict__ out)
{
    const int warp = blockIdx.x * 8 + (threadIdx.x >> 5);
    if (warp >= NN) return;
    const int lane = threadIdx.x & 31;

    const int start = g_off[warp];
    const int end   = g_off[warp + 1];

    float4 acc = make_float4(0.f, 0.f, 0.f, 0.f);

    for (int e0 = start; e0 < end; e0 += 32) {
        const int n = min(32, end - e0);
        int   c = 0;
        float v = 0.f;
        if (lane < n) {
            const int2 ed = g_edge[e0 + lane];
            c = ed.x;
            v = __int_as_float(ed.y);
        }
#pragma unroll 4
        for (int j = 0; j < n; j++) {
            const int   cj = __shfl_sync(0xffffffffu, c, j);
            const float vj = __shfl_sync(0xffffffffu, v, j);
            const uint2 hv = *(const uint2*)&g_feat[(size_t)cj * COUT + lane * 4];
            const float2 f0 = __half22float2(*(const __half2*)&hv.x);
            const float2 f1 = __half22float2(*(const __half2*)&hv.y);
            acc.x = fmaf(vj, f0.x, acc.x);
            acc.y = fmaf(vj, f0.y, acc.y);
            acc.z = fmaf(vj, f1.x, acc.z);
            acc.w = fmaf(vj, f1.y, acc.w);
        }
    }

    const float4 b = ((const float4*)bias)[lane];
    const float4 m = ((const float4*)mask2)[(size_t)warp * 32 + lane];
    const float  a = prelu_a[0];

    float4 o;
    o.x = (acc.x + b.x) * m.x;
    o.y = (acc.y + b.y) * m.y;
    o.z = (acc.z + b.z) * m.z;
    o.w = (acc.w + b.w) * m.w;
    o.x = o.x > 0.f ? o.x : a * o.x;
    o.y = o.y > 0.f ? o.y : a * o.y;
    o.z = o.z > 0.f ? o.z : a * o.z;
    o.w = o.w > 0.f ? o.w : a * o.w;

    ((float4*)out)[(size_t)warp * 32 + lane] = o;
}

// ---------------- launch (fork-join: CSR build overlaps GEMM) ----------------
static cudaStream_t s_side = nullptr;
static cudaEvent_t  s_evFork = nullptr;
static cudaEvent_t  s_evJoin = nullptr;

extern "C" void kernel_launch(void* const* d_in, const int* in_sizes, int n_in,
                              void* d_out, int out_size)
{
    const float* emb     = (const float*)d_in[0];
    const float* vals    = (const float*)d_in[1];
    const float* W       = (const float*)d_in[2];
    const float* b_fc    = (const float*)d_in[3];
    const float* bias    = (const float*)d_in[4];
    const float* prelu_a = (const float*)d_in[5];
    const float* mask1   = (const float*)d_in[6];
    const float* mask2   = (const float*)d_in[7];
    const int*   rows    = (const int*)d_in[8];
    const int*   cols    = (const int*)d_in[9];
    float*       out     = (float*)d_out;

    if (s_side == nullptr) {   // host-side infra init (first, uncaptured call)
        cudaStreamCreateWithFlags(&s_side, cudaStreamNonBlocking);
        cudaEventCreateWithFlags(&s_evFork, cudaEventDisableTiming);
        cudaEventCreateWithFlags(&s_evJoin, cudaEventDisableTiming);
    }

    // Fork side stream off the (captured) legacy stream
    cudaEventRecord(s_evFork, 0);
    cudaStreamWaitEvent(s_side, s_evFork, 0);

    // Branch A (legacy stream): GEMM via tf32 mma.sync
    gemm_mma_kernel<<<(NN + 127) / 128, 256>>>(emb, mask1, W, b_fc);

    // Branch B (side stream): CSR build (4 launches)
    hist_kernel<<<(EE + 255) / 256, 256, 0, s_side>>>(rows);
    scanA_kernel<<<SCAN_NB, SCAN_B, 0, s_side>>>();
    finalize_kernel<<<SCAN_NB, SCAN_B, 0, s_side>>>();
    scatter_kernel<<<(EE + 255) / 256, 256, 0, s_side>>>(rows, cols, vals);

    // Join
    cudaEventRecord(s_evJoin, s_side);
    cudaStreamWaitEvent(0, s_evJoin, 0);

    // SpMM + epilogue (warp per row)
    spmm_kernel<<<(NN + 7) / 8, 256>>>(bias, mask2, prelu_a, out);
}